// round 8
// baseline (speedup 1.0000x reference)
#include <cuda_runtime.h>

// ---------------- problem constants ----------------
#define Nn   50000
#define Ne   800000
#define IND  256
#define H1n  4
#define C1n  32
#define D1   128        // H1n*C1n
#define OUTD 40
#define NEG  0.2f

// ---------------- scratch (device globals; no allocation allowed) -------
__device__ __align__(16) float g_h1[Nn * D1];     // x @ W1
__device__ __align__(16) float g_h2[Nn * D1];     // elu(gat1 out)
__device__ __align__(16) float g_z2[Nn * OUTD];   // h2 @ W2
__device__ __align__(16) float g_als1[H1n * Nn];  // head-major
__device__ __align__(16) float g_ald1[H1n * Nn];  // head-major
__device__ float g_als2[Nn];
__device__ float g_ald2[Nn];
__device__ __align__(16) int g_cnt[Nn];
__device__ int   g_off[Nn + 1];
__device__ int   g_woff[Nn];
__device__ int   g_csr[Ne];

// ---------------- helpers ----------------
__device__ __forceinline__ float lrelu(float x) { return x > 0.f ? x : NEG * x; }

__device__ __forceinline__ unsigned f2tf(float f) {
    unsigned r;
    asm("cvt.rna.tf32.f32 %0, %1;" : "=r"(r) : "f"(f));
    return r;
}

__device__ __forceinline__ void mma_tf32(float c[4],
                                         unsigned a0, unsigned a1, unsigned a2, unsigned a3,
                                         unsigned b0, unsigned b1) {
    asm volatile(
        "mma.sync.aligned.m16n8k8.row.col.f32.tf32.tf32.f32 "
        "{%0,%1,%2,%3},{%4,%5,%6,%7},{%8,%9},{%0,%1,%2,%3};"
        : "+f"(c[0]), "+f"(c[1]), "+f"(c[2]), "+f"(c[3])
        : "r"(a0), "r"(a1), "r"(a2), "r"(a3), "r"(b0), "r"(b1));
}

// ---------------- CSR build ----------------
__global__ void zero_cnt_kernel() {
    int i = blockIdx.x * blockDim.x + threadIdx.x;   // int4 index
    if (i * 4 < Nn) *(int4*)&g_cnt[i * 4] = make_int4(0, 0, 0, 0);
}

__global__ void hist_kernel(const int* __restrict__ ei) {
    int base = (blockIdx.x * blockDim.x + threadIdx.x) * 4;
    if (base + 4 <= Ne) {
        int4 d = *(const int4*)&ei[Ne + base];
        atomicAdd(&g_cnt[d.x], 1);
        atomicAdd(&g_cnt[d.y], 1);
        atomicAdd(&g_cnt[d.z], 1);
        atomicAdd(&g_cnt[d.w], 1);
    } else {
        for (int e = base; e < Ne; e++) atomicAdd(&g_cnt[ei[Ne + e]], 1);
    }
}

__global__ void scan_kernel() {
    const int T = 1024;
    int t = threadIdx.x;
    const int per = (Nn + T - 1) / T;
    int start = t * per;
    int end = min(start + per, Nn);
    int local = 0;
    for (int i = start; i < end; i++) local += g_cnt[i];

    int lane = t & 31, wid = t >> 5;
    int v = local;
#pragma unroll
    for (int o = 1; o < 32; o <<= 1) {
        int n = __shfl_up_sync(0xffffffffu, v, o);
        if (lane >= o) v += n;
    }
    __shared__ int wsum[32];
    if (lane == 31) wsum[wid] = v;
    __syncthreads();
    if (wid == 0) {
        int w = wsum[lane];
#pragma unroll
        for (int o = 1; o < 32; o <<= 1) {
            int n = __shfl_up_sync(0xffffffffu, w, o);
            if (lane >= o) w += n;
        }
        wsum[lane] = w;
    }
    __syncthreads();
    int incl = v + (wid > 0 ? wsum[wid - 1] : 0);
    int run = incl - local;
    for (int i = start; i < end; i++) {
        int c = g_cnt[i];
        g_off[i] = run;
        g_woff[i] = run;
        run += c;
    }
    if (t == T - 1) g_off[Nn] = run;
}

__global__ void scatter_kernel(const int* __restrict__ ei) {
    int base = (blockIdx.x * blockDim.x + threadIdx.x) * 4;
    if (base + 4 <= Ne) {
        int4 s = *(const int4*)&ei[base];
        int4 d = *(const int4*)&ei[Ne + base];
        int p0 = atomicAdd(&g_woff[d.x], 1);
        int p1 = atomicAdd(&g_woff[d.y], 1);
        int p2 = atomicAdd(&g_woff[d.z], 1);
        int p3 = atomicAdd(&g_woff[d.w], 1);
        g_csr[p0] = s.x;
        g_csr[p1] = s.y;
        g_csr[p2] = s.z;
        g_csr[p3] = s.w;
    } else {
        for (int e = base; e < Ne; e++) {
            int p = atomicAdd(&g_woff[ei[Ne + e]], 1);
            g_csr[p] = ei[e];
        }
    }
}

// ---------------- GEMM1 (tf32, register-prefetch pipelined) ----------------
// 50000x256 @ 256x128, block tile 128x128, BK=32, 8 warps (4 m x 2 n).
#define G1_LOAD(K0)                                                                  \
    do {                                                                             \
        _Pragma("unroll") for (int i = 0; i < 4; i++) {                              \
            int idx = tid + i * 256;                                                 \
            int r = idx >> 3, c4 = idx & 7;                                          \
            int grow = rowBase + r;                                                  \
            pa[i] = (grow < Nn) ? *(const float4*)(x + grow * IND + (K0) + c4 * 4)   \
                                : make_float4(0.f, 0.f, 0.f, 0.f);                   \
        }                                                                            \
        _Pragma("unroll") for (int i = 0; i < 4; i++) {                              \
            int idx = tid + i * 256;                                                 \
            int r = idx >> 5, c4 = idx & 31;                                         \
            pb[i] = *(const float4*)(W + ((K0) + r) * D1 + c4 * 4);                  \
        }                                                                            \
    } while (0)

__global__ void gemm1_tf32_kernel(const float* __restrict__ x, const float* __restrict__ W) {
    __shared__ unsigned As[32][132];   // [k][m]
    __shared__ unsigned Bs[32][132];   // [k][n]
    int tid = threadIdx.x;
    int w = tid >> 5, lane = tid & 31;
    int gid = lane >> 2, tig = lane & 3;
    int mbase = (w & 3) * 32;
    int nbase = (w >> 2) * 64;
    int rowBase = blockIdx.x * 128;

    float acc[2][8][4];
#pragma unroll
    for (int mt = 0; mt < 2; mt++)
#pragma unroll
        for (int nt = 0; nt < 8; nt++)
#pragma unroll
            for (int i = 0; i < 4; i++) acc[mt][nt][i] = 0.f;

    float4 pa[4], pb[4];
    G1_LOAD(0);

    for (int k0 = 0; k0 < IND; k0 += 32) {
        // store staged regs into smem (tf32 convert)
#pragma unroll
        for (int i = 0; i < 4; i++) {
            int idx = tid + i * 256;
            int r = idx >> 3, c4 = idx & 7;
            As[c4 * 4 + 0][r] = f2tf(pa[i].x);
            As[c4 * 4 + 1][r] = f2tf(pa[i].y);
            As[c4 * 4 + 2][r] = f2tf(pa[i].z);
            As[c4 * 4 + 3][r] = f2tf(pa[i].w);
        }
#pragma unroll
        for (int i = 0; i < 4; i++) {
            int idx = tid + i * 256;
            int r = idx >> 5, c4 = idx & 31;
            uint4 u;
            u.x = f2tf(pb[i].x); u.y = f2tf(pb[i].y); u.z = f2tf(pb[i].z); u.w = f2tf(pb[i].w);
            *(uint4*)&Bs[r][c4 * 4] = u;
        }
        __syncthreads();
        if (k0 + 32 < IND) G1_LOAD(k0 + 32);   // overlap with compute below

#pragma unroll
        for (int kk = 0; kk < 4; kk++) {
            int k = kk * 8;
            unsigned a[2][4];
#pragma unroll
            for (int mt = 0; mt < 2; mt++) {
                int m0 = mbase + mt * 16 + gid;
                a[mt][0] = As[k + tig][m0];
                a[mt][1] = As[k + tig][m0 + 8];
                a[mt][2] = As[k + tig + 4][m0];
                a[mt][3] = As[k + tig + 4][m0 + 8];
            }
            unsigned b[8][2];
#pragma unroll
            for (int nt = 0; nt < 8; nt++) {
                int n0 = nbase + nt * 8 + gid;
                b[nt][0] = Bs[k + tig][n0];
                b[nt][1] = Bs[k + tig + 4][n0];
            }
#pragma unroll
            for (int mt = 0; mt < 2; mt++)
#pragma unroll
                for (int nt = 0; nt < 8; nt++)
                    mma_tf32(acc[mt][nt], a[mt][0], a[mt][1], a[mt][2], a[mt][3],
                             b[nt][0], b[nt][1]);
        }
        __syncthreads();
    }
#pragma unroll
    for (int mt = 0; mt < 2; mt++) {
        int r0 = rowBase + mbase + mt * 16 + gid;
#pragma unroll
        for (int nt = 0; nt < 8; nt++) {
            int col = nbase + nt * 8 + tig * 2;
            if (r0 < Nn)
                *(float2*)&g_h1[r0 * D1 + col] = make_float2(acc[mt][nt][0], acc[mt][nt][1]);
            if (r0 + 8 < Nn)
                *(float2*)&g_h1[(r0 + 8) * D1 + col] = make_float2(acc[mt][nt][2], acc[mt][nt][3]);
        }
    }
}

// ---------------- layer-1 attention logits (head-major output) ----------------
__global__ void al1_kernel(const float* __restrict__ as1, const float* __restrict__ ad1) {
    int node = (blockIdx.x * blockDim.x + threadIdx.x) >> 5;
    int lane = threadIdx.x & 31;
    if (node >= Nn) return;
    float4 h = *(const float4*)&g_h1[node * D1 + lane * 4];
    float4 a = *(const float4*)&as1[lane * 4];
    float4 b = *(const float4*)&ad1[lane * 4];
    float ps = h.x * a.x + h.y * a.y + h.z * a.z + h.w * a.w;
    float pd = h.x * b.x + h.y * b.y + h.z * b.z + h.w * b.w;
#pragma unroll
    for (int o = 4; o > 0; o >>= 1) {
        ps += __shfl_down_sync(0xffffffffu, ps, o, 8);
        pd += __shfl_down_sync(0xffffffffu, pd, o, 8);
    }
    if ((lane & 7) == 0) {
        int hd = lane >> 3;
        g_als1[hd * Nn + node] = ps;
        g_ald1[hd * Nn + node] = pd;
    }
}

// ---------------- layer-1 GAT: warp per dst, 8-edge chunks ----------------
// Per chunk: 32 lanes compute pj=exp(lrelu(.)) for 8 edges x 4 heads in
// parallel (zero redundancy), then the serial loop is shfl + coalesced h row
// load + FMA only. Logits are tiny, so exp without max-subtract is exact.
__global__ void gat1_kernel(const float* __restrict__ b1) {
    int d = (blockIdx.x * blockDim.x + threadIdx.x) >> 5;
    int lane = threadIdx.x & 31;
    if (d >= Nn) return;
    int hd = lane >> 3;
    int sub = lane & 7;     // edge slot within chunk
    int grp = lane & 24;    // 8*hd

    const float* __restrict__ als_h = &g_als1[hd * Nn];
    float aldh = g_ald1[hd * Nn + d];
    // self-loop
    float pe = __expf(lrelu(als_h[d] + aldh));
    float s = pe;
    float4 hv = *(const float4*)&g_h1[d * D1 + lane * 4];
    float a0 = pe * hv.x, a1 = pe * hv.y, a2 = pe * hv.z, a3 = pe * hv.w;

    int beg = g_off[d];
    int deg = g_off[d + 1] - beg;

    for (int base = 0; base < deg; base += 8) {
        int idx = base + sub;
        bool valid = idx < deg;
        int sc_l = valid ? g_csr[beg + idx] : 0;
        float pj_l = valid ? __expf(lrelu(als_h[sc_l] + aldh)) : 0.f;
#pragma unroll
        for (int j = 0; j < 8; j++) {
            int sc = __shfl_sync(0xffffffffu, sc_l, grp + j);
            float pj = __shfl_sync(0xffffffffu, pj_l, grp + j);
            float4 h = *(const float4*)&g_h1[sc * D1 + lane * 4];
            s += pj;
            a0 += pj * h.x;
            a1 += pj * h.y;
            a2 += pj * h.z;
            a3 += pj * h.w;
        }
    }
    float inv = 1.f / s;
    float4 bb = *(const float4*)&b1[lane * 4];
    float v0 = a0 * inv + bb.x;
    float v1 = a1 * inv + bb.y;
    float v2 = a2 * inv + bb.z;
    float v3 = a3 * inv + bb.w;
    v0 = v0 > 0.f ? v0 : __expf(v0) - 1.f;
    v1 = v1 > 0.f ? v1 : __expf(v1) - 1.f;
    v2 = v2 > 0.f ? v2 : __expf(v2) - 1.f;
    v3 = v3 > 0.f ? v3 : __expf(v3) - 1.f;
    *(float4*)&g_h2[d * D1 + lane * 4] = make_float4(v0, v1, v2, v3);
}

// ---------------- GEMM2 + fused layer-2 logits ----------------
// g_z2 = g_h2 @ W2 (50000x128 @ 128x40); als2/ald2 computed from the
// register-resident accumulators (kills the separate al2 kernel + 8MB reread).
__global__ void gemm2_kernel(const float* __restrict__ W2,
                             const float* __restrict__ as2,
                             const float* __restrict__ ad2) {
    extern __shared__ float sm2[];
    float* sWt = sm2;               // [40][132] transposed W2
    float* sRow = sm2 + 40 * 132;   // [128][132]
    int tid = threadIdx.x;          // 256
    int nodeBase = blockIdx.x * 128;

    for (int i = tid; i < OUTD * D1; i += 256) {
        int c = i >> 7, k = i & 127;
        sWt[c * 132 + k] = W2[k * OUTD + c];
    }
#pragma unroll
    for (int i = 0; i < 16; i++) {
        int idx = tid + i * 256;
        int r = idx >> 5, c4 = idx & 31;
        int n = nodeBase + r;
        float4 v = make_float4(0.f, 0.f, 0.f, 0.f);
        if (n < Nn) v = *(const float4*)&g_h2[n * D1 + c4 * 4];
        *(float4*)&sRow[r * 132 + c4 * 4] = v;
    }
    __syncthreads();

    int r = tid >> 3, c0 = (tid & 7) * 5;
    float acc[4][5];
#pragma unroll
    for (int rr = 0; rr < 4; rr++)
#pragma unroll
        for (int c = 0; c < 5; c++) acc[rr][c] = 0.f;

    for (int k4 = 0; k4 < 32; k4++) {
        float4 wv[5];
#pragma unroll
        for (int c = 0; c < 5; c++) wv[c] = *(const float4*)&sWt[(c0 + c) * 132 + k4 * 4];
#pragma unroll
        for (int rr = 0; rr < 4; rr++) {
            float4 hv = *(const float4*)&sRow[(r + rr * 32) * 132 + k4 * 4];
#pragma unroll
            for (int c = 0; c < 5; c++)
                acc[rr][c] += hv.x * wv[c].x + hv.y * wv[c].y + hv.z * wv[c].z + hv.w * wv[c].w;
        }
    }
    float a_s[5], a_d[5];
#pragma unroll
    for (int c = 0; c < 5; c++) { a_s[c] = as2[c0 + c]; a_d[c] = ad2[c0 + c]; }
#pragma unroll
    for (int rr = 0; rr < 4; rr++) {
        int n = nodeBase + r + rr * 32;
        if (n < Nn) {
#pragma unroll
            for (int c = 0; c < 5; c++) g_z2[n * OUTD + c0 + c] = acc[rr][c];
        }
        float ps = 0.f, pd = 0.f;
#pragma unroll
        for (int c = 0; c < 5; c++) { ps += acc[rr][c] * a_s[c]; pd += acc[rr][c] * a_d[c]; }
#pragma unroll
        for (int o = 4; o > 0; o >>= 1) {
            ps += __shfl_down_sync(0xffffffffu, ps, o, 8);
            pd += __shfl_down_sync(0xffffffffu, pd, o, 8);
        }
        if ((tid & 7) == 0 && n < Nn) {
            g_als2[n] = ps;
            g_ald2[n] = pd;
        }
    }
}

// ---------------- layer-2 GAT (8-edge chunks) + fused log_softmax ----------------
__global__ void gat2_kernel(const float* __restrict__ b2, float* __restrict__ out) {
    int d = (blockIdx.x * blockDim.x + threadIdx.x) >> 5;
    int lane = threadIdx.x & 31;
    if (d >= Nn) return;
    int sub = lane & 7;

    float ald = g_ald2[d];
    float pe = __expf(lrelu(g_als2[d] + ald));
    float s = pe;
    float a0 = pe * g_z2[d * OUTD + lane];
    float a1 = (lane < 8) ? pe * g_z2[d * OUTD + 32 + lane] : 0.f;

    int beg = g_off[d];
    int deg = g_off[d + 1] - beg;

    for (int base = 0; base < deg; base += 8) {
        int idx = base + sub;
        bool valid = idx < deg;
        int sc_l = valid ? g_csr[beg + idx] : 0;
        float pj_l = valid ? __expf(lrelu(g_als2[sc_l] + ald)) : 0.f;
#pragma unroll
        for (int j = 0; j < 8; j++) {
            int sc = __shfl_sync(0xffffffffu, sc_l, j);
            float pj = __shfl_sync(0xffffffffu, pj_l, j);
            s += pj;
            a0 += pj * g_z2[sc * OUTD + lane];
            if (lane < 8) a1 += pj * g_z2[sc * OUTD + 32 + lane];
        }
    }
    float inv = 1.f / s;
    float v0 = a0 * inv + b2[lane];
    float v1 = (lane < 8) ? a1 * inv + b2[32 + lane] : -1e30f;

    float mx = fmaxf(v0, v1);
#pragma unroll
    for (int o = 16; o > 0; o >>= 1) mx = fmaxf(mx, __shfl_xor_sync(0xffffffffu, mx, o));
    float sum = __expf(v0 - mx) + ((lane < 8) ? __expf(v1 - mx) : 0.f);
#pragma unroll
    for (int o = 16; o > 0; o >>= 1) sum += __shfl_xor_sync(0xffffffffu, sum, o);
    float lse = __logf(sum);
    out[d * OUTD + lane] = v0 - mx - lse;
    if (lane < 8) out[d * OUTD + 32 + lane] = v1 - mx - lse;
}

// ---------------- launcher ----------------
extern "C" void kernel_launch(void* const* d_in, const int* in_sizes, int n_in,
                              void* d_out, int out_size) {
    const float* x   = (const float*)d_in[0];
    const int*   ei  = (const int*)d_in[1];
    const float* W1  = (const float*)d_in[2];
    const float* as1 = (const float*)d_in[3];
    const float* ad1 = (const float*)d_in[4];
    const float* b1  = (const float*)d_in[5];
    const float* W2  = (const float*)d_in[6];
    const float* as2 = (const float*)d_in[7];
    const float* ad2 = (const float*)d_in[8];
    const float* b2  = (const float*)d_in[9];
    float* out = (float*)d_out;
    (void)in_sizes; (void)n_in; (void)out_size;

    static bool attr_set = false;
    if (!attr_set) {
        cudaFuncSetAttribute(gemm2_kernel, cudaFuncAttributeMaxDynamicSharedMemorySize,
                             (40 * 132 + 128 * 132) * 4);
        attr_set = true;
    }

    // CSR-by-dst build (4 edges/thread for MLP)
    zero_cnt_kernel<<<(Nn / 4 + 255) / 256, 256>>>();
    hist_kernel<<<(Ne / 4 + 255) / 256, 256>>>(ei);
    scan_kernel<<<1, 1024>>>();
    scatter_kernel<<<(Ne / 4 + 255) / 256, 256>>>(ei);

    // layer 1
    gemm1_tf32_kernel<<<(Nn + 127) / 128, 256>>>(x, W1);
    al1_kernel<<<(Nn + 7) / 8, 256>>>(as1, ad1);
    gat1_kernel<<<(Nn + 7) / 8, 256>>>(b1);

    // layer 2
    gemm2_kernel<<<(Nn + 127) / 128, 256, (40 * 132 + 128 * 132) * 4>>>(W2, as2, ad2);
    gat2_kernel<<<(Nn + 7) / 8, 256>>>(b2, out);
}

// round 9
// speedup vs baseline: 1.4036x; 1.4036x over previous
#include <cuda_runtime.h>

// ---------------- problem constants ----------------
#define Nn   50000
#define Ne   800000
#define IND  256
#define H1n  4
#define C1n  32
#define D1   128        // H1n*C1n
#define OUTD 40
#define NEG  0.2f

#define G1_BLOCKS 391           // ceil(50000/128)
#define Z_BLOCKS  49            // ceil(12500 int4 / 256)
#define AL1_BLOCKS 6250         // ceil(50000/8)
#define HIST_BLOCKS 782         // ceil(200000/256)
#define SCAN_BLOCKS 196         // ceil(50000/256)

// ---------------- scratch (device globals; no allocation allowed) -------
__device__ __align__(16) float g_h1[Nn * D1];     // x @ W1
__device__ __align__(16) float g_h2[Nn * D1];     // elu(gat1 out)
__device__ __align__(16) float g_z2[Nn * OUTD];   // h2 @ W2
__device__ __align__(16) float g_als1[H1n * Nn];  // head-major
__device__ __align__(16) float g_ald1[H1n * Nn];  // head-major
__device__ float g_als2[Nn];
__device__ float g_ald2[Nn];
__device__ __align__(16) int g_cnt[Nn];
__device__ int   g_off[Nn + 1];
__device__ int   g_woff[Nn];
__device__ int   g_bsum[SCAN_BLOCKS];
__device__ int   g_csr[Ne];

// ---------------- helpers ----------------
__device__ __forceinline__ float lrelu(float x) { return x > 0.f ? x : NEG * x; }

__device__ __forceinline__ unsigned f2tf(float f) {
    unsigned r;
    asm("cvt.rna.tf32.f32 %0, %1;" : "=r"(r) : "f"(f));
    return r;
}

__device__ __forceinline__ void mma_tf32(float c[4],
                                         unsigned a0, unsigned a1, unsigned a2, unsigned a3,
                                         unsigned b0, unsigned b1) {
    asm volatile(
        "mma.sync.aligned.m16n8k8.row.col.f32.tf32.tf32.f32 "
        "{%0,%1,%2,%3},{%4,%5,%6,%7},{%8,%9},{%0,%1,%2,%3};"
        : "+f"(c[0]), "+f"(c[1]), "+f"(c[2]), "+f"(c[3])
        : "r"(a0), "r"(a1), "r"(a2), "r"(a3), "r"(b0), "r"(b1));
}

// =================================================================
// K1: gemm1 (blocks 0..390)  ||  zero g_cnt (blocks 391..439)
// =================================================================
#define G1_LOAD(K0)                                                                  \
    do {                                                                             \
        _Pragma("unroll") for (int i = 0; i < 4; i++) {                              \
            int idx = tid + i * 256;                                                 \
            int r = idx >> 3, c4 = idx & 7;                                          \
            int grow = rowBase + r;                                                  \
            pa[i] = (grow < Nn) ? *(const float4*)(x + grow * IND + (K0) + c4 * 4)   \
                                : make_float4(0.f, 0.f, 0.f, 0.f);                   \
        }                                                                            \
        _Pragma("unroll") for (int i = 0; i < 4; i++) {                              \
            int idx = tid + i * 256;                                                 \
            int r = idx >> 5, c4 = idx & 31;                                         \
            pb[i] = *(const float4*)(W + ((K0) + r) * D1 + c4 * 4);                  \
        }                                                                            \
    } while (0)

__global__ void gemm1_zero_kernel(const float* __restrict__ x, const float* __restrict__ W) {
    int tid = threadIdx.x;
    if (blockIdx.x >= G1_BLOCKS) {
        int i = (blockIdx.x - G1_BLOCKS) * 256 + tid;   // int4 index
        if (i * 4 < Nn) *(int4*)&g_cnt[i * 4] = make_int4(0, 0, 0, 0);
        return;
    }
    __shared__ unsigned As[32][132];   // [k][m]
    __shared__ unsigned Bs[32][132];   // [k][n]
    int w = tid >> 5, lane = tid & 31;
    int gid = lane >> 2, tig = lane & 3;
    int mbase = (w & 3) * 32;
    int nbase = (w >> 2) * 64;
    int rowBase = blockIdx.x * 128;

    float acc[2][8][4];
#pragma unroll
    for (int mt = 0; mt < 2; mt++)
#pragma unroll
        for (int nt = 0; nt < 8; nt++)
#pragma unroll
            for (int i = 0; i < 4; i++) acc[mt][nt][i] = 0.f;

    float4 pa[4], pb[4];
    G1_LOAD(0);

    for (int k0 = 0; k0 < IND; k0 += 32) {
#pragma unroll
        for (int i = 0; i < 4; i++) {
            int idx = tid + i * 256;
            int r = idx >> 3, c4 = idx & 7;
            As[c4 * 4 + 0][r] = f2tf(pa[i].x);
            As[c4 * 4 + 1][r] = f2tf(pa[i].y);
            As[c4 * 4 + 2][r] = f2tf(pa[i].z);
            As[c4 * 4 + 3][r] = f2tf(pa[i].w);
        }
#pragma unroll
        for (int i = 0; i < 4; i++) {
            int idx = tid + i * 256;
            int r = idx >> 5, c4 = idx & 31;
            uint4 u;
            u.x = f2tf(pb[i].x); u.y = f2tf(pb[i].y); u.z = f2tf(pb[i].z); u.w = f2tf(pb[i].w);
            *(uint4*)&Bs[r][c4 * 4] = u;
        }
        __syncthreads();
        if (k0 + 32 < IND) G1_LOAD(k0 + 32);

#pragma unroll
        for (int kk = 0; kk < 4; kk++) {
            int k = kk * 8;
            unsigned a[2][4];
#pragma unroll
            for (int mt = 0; mt < 2; mt++) {
                int m0 = mbase + mt * 16 + gid;
                a[mt][0] = As[k + tig][m0];
                a[mt][1] = As[k + tig][m0 + 8];
                a[mt][2] = As[k + tig + 4][m0];
                a[mt][3] = As[k + tig + 4][m0 + 8];
            }
            unsigned b[8][2];
#pragma unroll
            for (int nt = 0; nt < 8; nt++) {
                int n0 = nbase + nt * 8 + gid;
                b[nt][0] = Bs[k + tig][n0];
                b[nt][1] = Bs[k + tig + 4][n0];
            }
#pragma unroll
            for (int mt = 0; mt < 2; mt++)
#pragma unroll
                for (int nt = 0; nt < 8; nt++)
                    mma_tf32(acc[mt][nt], a[mt][0], a[mt][1], a[mt][2], a[mt][3],
                             b[nt][0], b[nt][1]);
        }
        __syncthreads();
    }
#pragma unroll
    for (int mt = 0; mt < 2; mt++) {
        int r0 = rowBase + mbase + mt * 16 + gid;
#pragma unroll
        for (int nt = 0; nt < 8; nt++) {
            int col = nbase + nt * 8 + tig * 2;
            if (r0 < Nn)
                *(float2*)&g_h1[r0 * D1 + col] = make_float2(acc[mt][nt][0], acc[mt][nt][1]);
            if (r0 + 8 < Nn)
                *(float2*)&g_h1[(r0 + 8) * D1 + col] = make_float2(acc[mt][nt][2], acc[mt][nt][3]);
        }
    }
}

// =================================================================
// K2: al1 (blocks 0..6249)  ||  hist (blocks 6250..7031)
// =================================================================
__global__ void al1_hist_kernel(const float* __restrict__ as1, const float* __restrict__ ad1,
                                const int* __restrict__ ei) {
    if (blockIdx.x >= AL1_BLOCKS) {
        int base = ((blockIdx.x - AL1_BLOCKS) * blockDim.x + threadIdx.x) * 4;
        if (base + 4 <= Ne) {
            int4 d = *(const int4*)&ei[Ne + base];
            atomicAdd(&g_cnt[d.x], 1);
            atomicAdd(&g_cnt[d.y], 1);
            atomicAdd(&g_cnt[d.z], 1);
            atomicAdd(&g_cnt[d.w], 1);
        } else {
            for (int e = base; e < Ne; e++) atomicAdd(&g_cnt[ei[Ne + e]], 1);
        }
        return;
    }
    int node = (blockIdx.x * blockDim.x + threadIdx.x) >> 5;
    int lane = threadIdx.x & 31;
    if (node >= Nn) return;
    float4 h = *(const float4*)&g_h1[node * D1 + lane * 4];
    float4 a = *(const float4*)&as1[lane * 4];
    float4 b = *(const float4*)&ad1[lane * 4];
    float ps = h.x * a.x + h.y * a.y + h.z * a.z + h.w * a.w;
    float pd = h.x * b.x + h.y * b.y + h.z * b.z + h.w * b.w;
#pragma unroll
    for (int o = 4; o > 0; o >>= 1) {
        ps += __shfl_down_sync(0xffffffffu, ps, o, 8);
        pd += __shfl_down_sync(0xffffffffu, pd, o, 8);
    }
    if ((lane & 7) == 0) {
        int hd = lane >> 3;
        g_als1[hd * Nn + node] = ps;
        g_ald1[hd * Nn + node] = pd;
    }
}

// =================================================================
// parallel exclusive scan of g_cnt: scanA (local) + scanC (apply)
// =================================================================
__global__ void scanA_kernel() {
    int b = blockIdx.x, t = threadIdx.x;
    int i = b * 256 + t;
    int v = (i < Nn) ? g_cnt[i] : 0;
    int lane = t & 31, wid = t >> 5;
    int incl = v;
#pragma unroll
    for (int o = 1; o < 32; o <<= 1) {
        int n = __shfl_up_sync(0xffffffffu, incl, o);
        if (lane >= o) incl += n;
    }
    __shared__ int ws[8];
    if (lane == 31) ws[wid] = incl;
    __syncthreads();
    if (t < 8) {
        int w = ws[t];
#pragma unroll
        for (int o = 1; o < 8; o <<= 1) {
            int n = __shfl_up_sync(0xffu, w, o);
            if ((t & 7) >= o) w += n;
        }
        ws[t] = w;
    }
    __syncthreads();
    int excl = incl - v + (wid > 0 ? ws[wid - 1] : 0);
    if (i < Nn) g_off[i] = excl;
    if (t == 255) g_bsum[b] = excl + v;
}

__global__ void scanC_kernel() {
    int b = blockIdx.x, t = threadIdx.x;
    // block offset = sum of block sums of preceding blocks (<=195 values)
    int v = (t < b) ? g_bsum[t] : 0;
    int lane = t & 31;
#pragma unroll
    for (int o = 16; o > 0; o >>= 1) v += __shfl_xor_sync(0xffffffffu, v, o);
    __shared__ int ws[8];
    if (lane == 0) ws[t >> 5] = v;
    __syncthreads();
    int off;
    {
        int s = 0;
#pragma unroll
        for (int k = 0; k < 8; k++) s += ws[k];
        off = s;
    }
    int i = b * 256 + t;
    if (i < Nn) {
        int o = g_off[i] + off;
        g_off[i] = o;
        g_woff[i] = o;
    }
    if (b == 0 && t == 0) g_off[Nn] = Ne;
}

__global__ void scatter_kernel(const int* __restrict__ ei) {
    int base = (blockIdx.x * blockDim.x + threadIdx.x) * 4;
    if (base + 4 <= Ne) {
        int4 s = *(const int4*)&ei[base];
        int4 d = *(const int4*)&ei[Ne + base];
        int p0 = atomicAdd(&g_woff[d.x], 1);
        int p1 = atomicAdd(&g_woff[d.y], 1);
        int p2 = atomicAdd(&g_woff[d.z], 1);
        int p3 = atomicAdd(&g_woff[d.w], 1);
        g_csr[p0] = s.x;
        g_csr[p1] = s.y;
        g_csr[p2] = s.z;
        g_csr[p3] = s.w;
    } else {
        for (int e = base; e < Ne; e++) {
            int p = atomicAdd(&g_woff[ei[Ne + e]], 1);
            g_csr[p] = ei[e];
        }
    }
}

// ---------------- layer-1 GAT: warp per dst, 8-edge chunks ----------------
__global__ void gat1_kernel(const float* __restrict__ b1) {
    int d = (blockIdx.x * blockDim.x + threadIdx.x) >> 5;
    int lane = threadIdx.x & 31;
    if (d >= Nn) return;
    int hd = lane >> 3;
    int sub = lane & 7;
    int grp = lane & 24;

    const float* __restrict__ als_h = &g_als1[hd * Nn];
    float aldh = g_ald1[hd * Nn + d];
    float pe = __expf(lrelu(als_h[d] + aldh));
    float s = pe;
    float4 hv = *(const float4*)&g_h1[d * D1 + lane * 4];
    float a0 = pe * hv.x, a1 = pe * hv.y, a2 = pe * hv.z, a3 = pe * hv.w;

    int beg = g_off[d];
    int deg = g_off[d + 1] - beg;

    for (int base = 0; base < deg; base += 8) {
        int idx = base + sub;
        bool valid = idx < deg;
        int sc_l = valid ? g_csr[beg + idx] : 0;
        float pj_l = valid ? __expf(lrelu(als_h[sc_l] + aldh)) : 0.f;
#pragma unroll
        for (int j = 0; j < 8; j++) {
            int sc = __shfl_sync(0xffffffffu, sc_l, grp + j);
            float pj = __shfl_sync(0xffffffffu, pj_l, grp + j);
            float4 h = *(const float4*)&g_h1[sc * D1 + lane * 4];
            s += pj;
            a0 += pj * h.x;
            a1 += pj * h.y;
            a2 += pj * h.z;
            a3 += pj * h.w;
        }
    }
    float inv = 1.f / s;
    float4 bb = *(const float4*)&b1[lane * 4];
    float v0 = a0 * inv + bb.x;
    float v1 = a1 * inv + bb.y;
    float v2 = a2 * inv + bb.z;
    float v3 = a3 * inv + bb.w;
    v0 = v0 > 0.f ? v0 : __expf(v0) - 1.f;
    v1 = v1 > 0.f ? v1 : __expf(v1) - 1.f;
    v2 = v2 > 0.f ? v2 : __expf(v2) - 1.f;
    v3 = v3 > 0.f ? v3 : __expf(v3) - 1.f;
    *(float4*)&g_h2[d * D1 + lane * 4] = make_float4(v0, v1, v2, v3);
}

// ---------------- GEMM2 + fused layer-2 logits ----------------
__global__ void gemm2_kernel(const float* __restrict__ W2,
                             const float* __restrict__ as2,
                             const float* __restrict__ ad2) {
    extern __shared__ float sm2[];
    float* sWt = sm2;               // [40][132]
    float* sRow = sm2 + 40 * 132;   // [128][132]
    int tid = threadIdx.x;
    int nodeBase = blockIdx.x * 128;

    for (int i = tid; i < OUTD * D1; i += 256) {
        int c = i >> 7, k = i & 127;
        sWt[c * 132 + k] = W2[k * OUTD + c];
    }
#pragma unroll
    for (int i = 0; i < 16; i++) {
        int idx = tid + i * 256;
        int r = idx >> 5, c4 = idx & 31;
        int n = nodeBase + r;
        float4 v = make_float4(0.f, 0.f, 0.f, 0.f);
        if (n < Nn) v = *(const float4*)&g_h2[n * D1 + c4 * 4];
        *(float4*)&sRow[r * 132 + c4 * 4] = v;
    }
    __syncthreads();

    int r = tid >> 3, c0 = (tid & 7) * 5;
    float acc[4][5];
#pragma unroll
    for (int rr = 0; rr < 4; rr++)
#pragma unroll
        for (int c = 0; c < 5; c++) acc[rr][c] = 0.f;

    for (int k4 = 0; k4 < 32; k4++) {
        float4 wv[5];
#pragma unroll
        for (int c = 0; c < 5; c++) wv[c] = *(const float4*)&sWt[(c0 + c) * 132 + k4 * 4];
#pragma unroll
        for (int rr = 0; rr < 4; rr++) {
            float4 hv = *(const float4*)&sRow[(r + rr * 32) * 132 + k4 * 4];
#pragma unroll
            for (int c = 0; c < 5; c++)
                acc[rr][c] += hv.x * wv[c].x + hv.y * wv[c].y + hv.z * wv[c].z + hv.w * wv[c].w;
        }
    }
    float a_s[5], a_d[5];
#pragma unroll
    for (int c = 0; c < 5; c++) { a_s[c] = as2[c0 + c]; a_d[c] = ad2[c0 + c]; }
#pragma unroll
    for (int rr = 0; rr < 4; rr++) {
        int n = nodeBase + r + rr * 32;
        if (n < Nn) {
#pragma unroll
            for (int c = 0; c < 5; c++) g_z2[n * OUTD + c0 + c] = acc[rr][c];
        }
        float ps = 0.f, pd = 0.f;
#pragma unroll
        for (int c = 0; c < 5; c++) { ps += acc[rr][c] * a_s[c]; pd += acc[rr][c] * a_d[c]; }
#pragma unroll
        for (int o = 4; o > 0; o >>= 1) {
            ps += __shfl_down_sync(0xffffffffu, ps, o, 8);
            pd += __shfl_down_sync(0xffffffffu, pd, o, 8);
        }
        if ((tid & 7) == 0 && n < Nn) {
            g_als2[n] = ps;
            g_ald2[n] = pd;
        }
    }
}

// ---------------- layer-2 GAT + fused log_softmax ----------------
__global__ void gat2_kernel(const float* __restrict__ b2, float* __restrict__ out) {
    int d = (blockIdx.x * blockDim.x + threadIdx.x) >> 5;
    int lane = threadIdx.x & 31;
    if (d >= Nn) return;
    int sub = lane & 7;

    float ald = g_ald2[d];
    float pe = __expf(lrelu(g_als2[d] + ald));
    float s = pe;
    float a0 = pe * g_z2[d * OUTD + lane];
    float a1 = (lane < 8) ? pe * g_z2[d * OUTD + 32 + lane] : 0.f;

    int beg = g_off[d];
    int deg = g_off[d + 1] - beg;

    for (int base = 0; base < deg; base += 8) {
        int idx = base + sub;
        bool valid = idx < deg;
        int sc_l = valid ? g_csr[beg + idx] : 0;
        float pj_l = valid ? __expf(lrelu(g_als2[sc_l] + ald)) : 0.f;
#pragma unroll
        for (int j = 0; j < 8; j++) {
            int sc = __shfl_sync(0xffffffffu, sc_l, j);
            float pj = __shfl_sync(0xffffffffu, pj_l, j);
            s += pj;
            a0 += pj * g_z2[sc * OUTD + lane];
            if (lane < 8) a1 += pj * g_z2[sc * OUTD + 32 + lane];
        }
    }
    float inv = 1.f / s;
    float v0 = a0 * inv + b2[lane];
    float v1 = (lane < 8) ? a1 * inv + b2[32 + lane] : -1e30f;

    float mx = fmaxf(v0, v1);
#pragma unroll
    for (int o = 16; o > 0; o >>= 1) mx = fmaxf(mx, __shfl_xor_sync(0xffffffffu, mx, o));
    float sum = __expf(v0 - mx) + ((lane < 8) ? __expf(v1 - mx) : 0.f);
#pragma unroll
    for (int o = 16; o > 0; o >>= 1) sum += __shfl_xor_sync(0xffffffffu, sum, o);
    float lse = __logf(sum);
    out[d * OUTD + lane] = v0 - mx - lse;
    if (lane < 8) out[d * OUTD + 32 + lane] = v1 - mx - lse;
}

// ---------------- launcher ----------------
extern "C" void kernel_launch(void* const* d_in, const int* in_sizes, int n_in,
                              void* d_out, int out_size) {
    const float* x   = (const float*)d_in[0];
    const int*   ei  = (const int*)d_in[1];
    const float* W1  = (const float*)d_in[2];
    const float* as1 = (const float*)d_in[3];
    const float* ad1 = (const float*)d_in[4];
    const float* b1  = (const float*)d_in[5];
    const float* W2  = (const float*)d_in[6];
    const float* as2 = (const float*)d_in[7];
    const float* ad2 = (const float*)d_in[8];
    const float* b2  = (const float*)d_in[9];
    float* out = (float*)d_out;
    (void)in_sizes; (void)n_in; (void)out_size;

    static bool attr_set = false;
    if (!attr_set) {
        cudaFuncSetAttribute(gemm2_kernel, cudaFuncAttributeMaxDynamicSharedMemorySize,
                             (40 * 132 + 128 * 132) * 4);
        attr_set = true;
    }

    // K1: gemm1 || zero_cnt
    gemm1_zero_kernel<<<G1_BLOCKS + Z_BLOCKS, 256>>>(x, W1);
    // K2: al1 || hist
    al1_hist_kernel<<<AL1_BLOCKS + HIST_BLOCKS, 256>>>(as1, ad1, ei);
    // parallel scan + scatter
    scanA_kernel<<<SCAN_BLOCKS, 256>>>();
    scanC_kernel<<<SCAN_BLOCKS, 256>>>();
    scatter_kernel<<<HIST_BLOCKS, 256>>>(ei);

    // layer 1 aggregation
    gat1_kernel<<<(Nn + 7) / 8, 256>>>(b1);

    // layer 2
    gemm2_kernel<<<(Nn + 127) / 128, 256, (40 * 132 + 128 * 132) * 4>>>(W2, as2, ad2);
    gat2_kernel<<<(Nn + 7) / 8, 256>>>(b2, out);
}

// round 10
// speedup vs baseline: 1.5037x; 1.0713x over previous
#include <cuda_runtime.h>
#include <cuda_bf16.h>

// ---------------- problem constants ----------------
#define Nn   50000
#define Ne   800000
#define IND  256
#define H1n  4
#define C1n  32
#define D1   128        // H1n*C1n
#define OUTD 40
#define NEG  0.2f

#define G1_BLOCKS 391           // ceil(50000/128)
#define Z_BLOCKS  49            // ceil(12500 int4 / 256)
#define AL1_BLOCKS 6250         // ceil(50000/8)
#define HIST_BLOCKS 782         // ceil(200000/256)
#define SCAN_BLOCKS 196         // ceil(50000/256)

// ---------------- scratch (device globals; no allocation allowed) -------
__device__ __align__(16) float g_h1[Nn * D1];            // x @ W1 (fp32)
__device__ __align__(16) __nv_bfloat162 g_h1b[Nn * 64];  // bf16 copy for gather
__device__ __align__(16) float g_h2[Nn * D1];            // elu(gat1 out)
__device__ __align__(16) __nv_bfloat16 g_z2b[Nn * OUTD]; // h2 @ W2 (bf16)
__device__ __align__(16) float g_als1[H1n * Nn];         // head-major
__device__ __align__(16) float g_ald1[H1n * Nn];         // head-major
__device__ float g_als2[Nn];
__device__ float g_ald2[Nn];
__device__ __align__(16) int g_cnt[Nn];
__device__ int   g_off[Nn + 1];
__device__ int   g_woff[Nn];
__device__ int   g_bsum[SCAN_BLOCKS];
__device__ int   g_csr[Ne];

// ---------------- helpers ----------------
__device__ __forceinline__ float lrelu(float x) { return x > 0.f ? x : NEG * x; }

__device__ __forceinline__ unsigned f2tf(float f) {
    unsigned r;
    asm("cvt.rna.tf32.f32 %0, %1;" : "=r"(r) : "f"(f));
    return r;
}

__device__ __forceinline__ void mma_tf32(float c[4],
                                         unsigned a0, unsigned a1, unsigned a2, unsigned a3,
                                         unsigned b0, unsigned b1) {
    asm volatile(
        "mma.sync.aligned.m16n8k8.row.col.f32.tf32.tf32.f32 "
        "{%0,%1,%2,%3},{%4,%5,%6,%7},{%8,%9},{%0,%1,%2,%3};"
        : "+f"(c[0]), "+f"(c[1]), "+f"(c[2]), "+f"(c[3])
        : "r"(a0), "r"(a1), "r"(a2), "r"(a3), "r"(b0), "r"(b1));
}

// ---------------- zero counts (tiny standalone so hist can overlap gemm1) ---
__global__ void zero_cnt_kernel() {
    int i = blockIdx.x * 256 + threadIdx.x;
    if (i * 4 < Nn) *(int4*)&g_cnt[i * 4] = make_int4(0, 0, 0, 0);
}

// =================================================================
// K1: gemm1 (blocks 0..390)  ||  hist (blocks 391..1172)
// =================================================================
#define G1_LOAD(K0)                                                                  \
    do {                                                                             \
        _Pragma("unroll") for (int i = 0; i < 4; i++) {                              \
            int idx = tid + i * 256;                                                 \
            int r = idx >> 3, c4 = idx & 7;                                          \
            int grow = rowBase + r;                                                  \
            pa[i] = (grow < Nn) ? *(const float4*)(x + grow * IND + (K0) + c4 * 4)   \
                                : make_float4(0.f, 0.f, 0.f, 0.f);                   \
        }                                                                            \
        _Pragma("unroll") for (int i = 0; i < 4; i++) {                              \
            int idx = tid + i * 256;                                                 \
            int r = idx >> 5, c4 = idx & 31;                                         \
            pb[i] = *(const float4*)(W + ((K0) + r) * D1 + c4 * 4);                  \
        }                                                                            \
    } while (0)

__global__ void gemm1_hist_kernel(const float* __restrict__ x, const float* __restrict__ W,
                                  const int* __restrict__ ei) {
    int tid = threadIdx.x;
    if (blockIdx.x >= G1_BLOCKS) {
        int base = ((blockIdx.x - G1_BLOCKS) * 256 + tid) * 4;
        if (base + 4 <= Ne) {
            int4 d = *(const int4*)&ei[Ne + base];
            atomicAdd(&g_cnt[d.x], 1);
            atomicAdd(&g_cnt[d.y], 1);
            atomicAdd(&g_cnt[d.z], 1);
            atomicAdd(&g_cnt[d.w], 1);
        } else {
            for (int e = base; e < Ne; e++) atomicAdd(&g_cnt[ei[Ne + e]], 1);
        }
        return;
    }
    __shared__ unsigned As[32][132];   // [k][m]
    __shared__ unsigned Bs[32][132];   // [k][n]
    int w = tid >> 5, lane = tid & 31;
    int gid = lane >> 2, tig = lane & 3;
    int mbase = (w & 3) * 32;
    int nbase = (w >> 2) * 64;
    int rowBase = blockIdx.x * 128;

    float acc[2][8][4];
#pragma unroll
    for (int mt = 0; mt < 2; mt++)
#pragma unroll
        for (int nt = 0; nt < 8; nt++)
#pragma unroll
            for (int i = 0; i < 4; i++) acc[mt][nt][i] = 0.f;

    float4 pa[4], pb[4];
    G1_LOAD(0);

    for (int k0 = 0; k0 < IND; k0 += 32) {
#pragma unroll
        for (int i = 0; i < 4; i++) {
            int idx = tid + i * 256;
            int r = idx >> 3, c4 = idx & 7;
            As[c4 * 4 + 0][r] = f2tf(pa[i].x);
            As[c4 * 4 + 1][r] = f2tf(pa[i].y);
            As[c4 * 4 + 2][r] = f2tf(pa[i].z);
            As[c4 * 4 + 3][r] = f2tf(pa[i].w);
        }
#pragma unroll
        for (int i = 0; i < 4; i++) {
            int idx = tid + i * 256;
            int r = idx >> 5, c4 = idx & 31;
            uint4 u;
            u.x = f2tf(pb[i].x); u.y = f2tf(pb[i].y); u.z = f2tf(pb[i].z); u.w = f2tf(pb[i].w);
            *(uint4*)&Bs[r][c4 * 4] = u;
        }
        __syncthreads();
        if (k0 + 32 < IND) G1_LOAD(k0 + 32);

#pragma unroll
        for (int kk = 0; kk < 4; kk++) {
            int k = kk * 8;
            unsigned a[2][4];
#pragma unroll
            for (int mt = 0; mt < 2; mt++) {
                int m0 = mbase + mt * 16 + gid;
                a[mt][0] = As[k + tig][m0];
                a[mt][1] = As[k + tig][m0 + 8];
                a[mt][2] = As[k + tig + 4][m0];
                a[mt][3] = As[k + tig + 4][m0 + 8];
            }
            unsigned b[8][2];
#pragma unroll
            for (int nt = 0; nt < 8; nt++) {
                int n0 = nbase + nt * 8 + gid;
                b[nt][0] = Bs[k + tig][n0];
                b[nt][1] = Bs[k + tig + 4][n0];
            }
#pragma unroll
            for (int mt = 0; mt < 2; mt++)
#pragma unroll
                for (int nt = 0; nt < 8; nt++)
                    mma_tf32(acc[mt][nt], a[mt][0], a[mt][1], a[mt][2], a[mt][3],
                             b[nt][0], b[nt][1]);
        }
        __syncthreads();
    }
#pragma unroll
    for (int mt = 0; mt < 2; mt++) {
        int r0 = rowBase + mbase + mt * 16 + gid;
#pragma unroll
        for (int nt = 0; nt < 8; nt++) {
            int col = nbase + nt * 8 + tig * 2;
            if (r0 < Nn) {
                *(float2*)&g_h1[r0 * D1 + col] = make_float2(acc[mt][nt][0], acc[mt][nt][1]);
                g_h1b[r0 * 64 + col / 2] = __floats2bfloat162_rn(acc[mt][nt][0], acc[mt][nt][1]);
            }
            if (r0 + 8 < Nn) {
                *(float2*)&g_h1[(r0 + 8) * D1 + col] = make_float2(acc[mt][nt][2], acc[mt][nt][3]);
                g_h1b[(r0 + 8) * 64 + col / 2] = __floats2bfloat162_rn(acc[mt][nt][2], acc[mt][nt][3]);
            }
        }
    }
}

// =================================================================
// K2: scanA (blocks 0..195, first so they start early)  ||  al1 (rest)
// =================================================================
__global__ void al1_scanA_kernel(const float* __restrict__ as1, const float* __restrict__ ad1) {
    int t = threadIdx.x;
    if (blockIdx.x < SCAN_BLOCKS) {
        int b = blockIdx.x;
        int i = b * 256 + t;
        int v = (i < Nn) ? g_cnt[i] : 0;
        int lane = t & 31, wid = t >> 5;
        int incl = v;
#pragma unroll
        for (int o = 1; o < 32; o <<= 1) {
            int n = __shfl_up_sync(0xffffffffu, incl, o);
            if (lane >= o) incl += n;
        }
        __shared__ int ws[8];
        if (lane == 31) ws[wid] = incl;
        __syncthreads();
        if (t < 8) {
            int w = ws[t];
#pragma unroll
            for (int o = 1; o < 8; o <<= 1) {
                int n = __shfl_up_sync(0xffu, w, o);
                if ((t & 7) >= o) w += n;
            }
            ws[t] = w;
        }
        __syncthreads();
        int excl = incl - v + (wid > 0 ? ws[wid - 1] : 0);
        if (i < Nn) g_off[i] = excl;
        if (t == 255) g_bsum[b] = excl + v;
        return;
    }
    int node = ((blockIdx.x - SCAN_BLOCKS) * 256 + t) >> 5;
    int lane = t & 31;
    if (node >= Nn) return;
    float4 h = *(const float4*)&g_h1[node * D1 + lane * 4];
    float4 a = *(const float4*)&as1[lane * 4];
    float4 b = *(const float4*)&ad1[lane * 4];
    float ps = h.x * a.x + h.y * a.y + h.z * a.z + h.w * a.w;
    float pd = h.x * b.x + h.y * b.y + h.z * b.z + h.w * b.w;
#pragma unroll
    for (int o = 4; o > 0; o >>= 1) {
        ps += __shfl_down_sync(0xffffffffu, ps, o, 8);
        pd += __shfl_down_sync(0xffffffffu, pd, o, 8);
    }
    if ((lane & 7) == 0) {
        int hd = lane >> 3;
        g_als1[hd * Nn + node] = ps;
        g_ald1[hd * Nn + node] = pd;
    }
}

__global__ void scanC_kernel() {
    int b = blockIdx.x, t = threadIdx.x;
    int v = (t < b) ? g_bsum[t] : 0;
    int lane = t & 31;
#pragma unroll
    for (int o = 16; o > 0; o >>= 1) v += __shfl_xor_sync(0xffffffffu, v, o);
    __shared__ int ws[8];
    if (lane == 0) ws[t >> 5] = v;
    __syncthreads();
    int off = 0;
#pragma unroll
    for (int k = 0; k < 8; k++) off += ws[k];
    int i = b * 256 + t;
    if (i < Nn) {
        int o = g_off[i] + off;
        g_off[i] = o;
        g_woff[i] = o;
    }
    if (b == 0 && t == 0) g_off[Nn] = Ne;
}

__global__ void scatter_kernel(const int* __restrict__ ei) {
    int base = (blockIdx.x * blockDim.x + threadIdx.x) * 4;
    if (base + 4 <= Ne) {
        int4 s = *(const int4*)&ei[base];
        int4 d = *(const int4*)&ei[Ne + base];
        int p0 = atomicAdd(&g_woff[d.x], 1);
        int p1 = atomicAdd(&g_woff[d.y], 1);
        int p2 = atomicAdd(&g_woff[d.z], 1);
        int p3 = atomicAdd(&g_woff[d.w], 1);
        g_csr[p0] = s.x;
        g_csr[p1] = s.y;
        g_csr[p2] = s.z;
        g_csr[p3] = s.w;
    } else {
        for (int e = base; e < Ne; e++) {
            int p = atomicAdd(&g_woff[ei[Ne + e]], 1);
            g_csr[p] = ei[e];
        }
    }
}

// ---------------- layer-1 GAT: warp per dst, bf16 gather ----------------
__global__ void gat1_kernel(const float* __restrict__ b1) {
    int d = (blockIdx.x * blockDim.x + threadIdx.x) >> 5;
    int lane = threadIdx.x & 31;
    if (d >= Nn) return;
    int hd = lane >> 3;
    int sub = lane & 7;
    int grp = lane & 24;

    const float* __restrict__ als_h = &g_als1[hd * Nn];
    float aldh = g_ald1[hd * Nn + d];
    float pe = __expf(lrelu(als_h[d] + aldh));
    float s = pe;
    float4 hv = *(const float4*)&g_h1[d * D1 + lane * 4];  // self: fp32 exact
    float a0 = pe * hv.x, a1 = pe * hv.y, a2 = pe * hv.z, a3 = pe * hv.w;

    int beg = g_off[d];
    int deg = g_off[d + 1] - beg;

    for (int base = 0; base < deg; base += 8) {
        int idx = base + sub;
        bool valid = idx < deg;
        int sc_l = valid ? g_csr[beg + idx] : 0;
        float pj_l = valid ? __expf(lrelu(als_h[sc_l] + aldh)) : 0.f;
#pragma unroll
        for (int j = 0; j < 8; j++) {
            int sc = __shfl_sync(0xffffffffu, sc_l, grp + j);
            float pj = __shfl_sync(0xffffffffu, pj_l, grp + j);
            const __nv_bfloat162* p = &g_h1b[sc * 64 + lane * 2];
            float2 x01 = __bfloat1622float2(p[0]);
            float2 x23 = __bfloat1622float2(p[1]);
            s += pj;
            a0 += pj * x01.x;
            a1 += pj * x01.y;
            a2 += pj * x23.x;
            a3 += pj * x23.y;
        }
    }
    float inv = 1.f / s;
    float4 bb = *(const float4*)&b1[lane * 4];
    float v0 = a0 * inv + bb.x;
    float v1 = a1 * inv + bb.y;
    float v2 = a2 * inv + bb.z;
    float v3 = a3 * inv + bb.w;
    v0 = v0 > 0.f ? v0 : __expf(v0) - 1.f;
    v1 = v1 > 0.f ? v1 : __expf(v1) - 1.f;
    v2 = v2 > 0.f ? v2 : __expf(v2) - 1.f;
    v3 = v3 > 0.f ? v3 : __expf(v3) - 1.f;
    *(float4*)&g_h2[d * D1 + lane * 4] = make_float4(v0, v1, v2, v3);
}

// ---------------- GEMM2 + fused layer-2 logits (bf16 z2 output) ----------------
__global__ void gemm2_kernel(const float* __restrict__ W2,
                             const float* __restrict__ as2,
                             const float* __restrict__ ad2) {
    extern __shared__ float sm2[];
    float* sWt = sm2;               // [40][132]
    float* sRow = sm2 + 40 * 132;   // [128][132]
    int tid = threadIdx.x;
    int nodeBase = blockIdx.x * 128;

    for (int i = tid; i < OUTD * D1; i += 256) {
        int c = i >> 7, k = i & 127;
        sWt[c * 132 + k] = W2[k * OUTD + c];
    }
#pragma unroll
    for (int i = 0; i < 16; i++) {
        int idx = tid + i * 256;
        int r = idx >> 5, c4 = idx & 31;
        int n = nodeBase + r;
        float4 v = make_float4(0.f, 0.f, 0.f, 0.f);
        if (n < Nn) v = *(const float4*)&g_h2[n * D1 + c4 * 4];
        *(float4*)&sRow[r * 132 + c4 * 4] = v;
    }
    __syncthreads();

    int r = tid >> 3, c0 = (tid & 7) * 5;
    float acc[4][5];
#pragma unroll
    for (int rr = 0; rr < 4; rr++)
#pragma unroll
        for (int c = 0; c < 5; c++) acc[rr][c] = 0.f;

    for (int k4 = 0; k4 < 32; k4++) {
        float4 wv[5];
#pragma unroll
        for (int c = 0; c < 5; c++) wv[c] = *(const float4*)&sWt[(c0 + c) * 132 + k4 * 4];
#pragma unroll
        for (int rr = 0; rr < 4; rr++) {
            float4 hv = *(const float4*)&sRow[(r + rr * 32) * 132 + k4 * 4];
#pragma unroll
            for (int c = 0; c < 5; c++)
                acc[rr][c] += hv.x * wv[c].x + hv.y * wv[c].y + hv.z * wv[c].z + hv.w * wv[c].w;
        }
    }
    float a_s[5], a_d[5];
#pragma unroll
    for (int c = 0; c < 5; c++) { a_s[c] = as2[c0 + c]; a_d[c] = ad2[c0 + c]; }
#pragma unroll
    for (int rr = 0; rr < 4; rr++) {
        int n = nodeBase + r + rr * 32;
        if (n < Nn) {
#pragma unroll
            for (int c = 0; c < 5; c++)
                g_z2b[n * OUTD + c0 + c] = __float2bfloat16_rn(acc[rr][c]);
        }
        float ps = 0.f, pd = 0.f;
#pragma unroll
        for (int c = 0; c < 5; c++) { ps += acc[rr][c] * a_s[c]; pd += acc[rr][c] * a_d[c]; }
#pragma unroll
        for (int o = 4; o > 0; o >>= 1) {
            ps += __shfl_down_sync(0xffffffffu, ps, o, 8);
            pd += __shfl_down_sync(0xffffffffu, pd, o, 8);
        }
        if ((tid & 7) == 0 && n < Nn) {
            g_als2[n] = ps;
            g_ald2[n] = pd;
        }
    }
}

// ---------------- layer-2 GAT (bf16 gather, lane<20 holds classes 2l,2l+1) ----
__global__ void gat2_kernel(const float* __restrict__ b2, float* __restrict__ out) {
    int d = (blockIdx.x * blockDim.x + threadIdx.x) >> 5;
    int lane = threadIdx.x & 31;
    if (d >= Nn) return;
    int sub = lane & 7;
    bool act = lane < 20;
    const __nv_bfloat162* __restrict__ zp = (const __nv_bfloat162*)g_z2b;

    float ald = g_ald2[d];
    float pe = __expf(lrelu(g_als2[d] + ald));
    float s = pe;
    float2 zs = act ? __bfloat1622float2(zp[d * 20 + lane]) : make_float2(0.f, 0.f);
    float a0 = pe * zs.x, a1 = pe * zs.y;

    int beg = g_off[d];
    int deg = g_off[d + 1] - beg;

    for (int base = 0; base < deg; base += 8) {
        int idx = base + sub;
        bool valid = idx < deg;
        int sc_l = valid ? g_csr[beg + idx] : 0;
        float pj_l = valid ? __expf(lrelu(g_als2[sc_l] + ald)) : 0.f;
#pragma unroll
        for (int j = 0; j < 8; j++) {
            int sc = __shfl_sync(0xffffffffu, sc_l, j);
            float pj = __shfl_sync(0xffffffffu, pj_l, j);
            float2 zv = act ? __bfloat1622float2(zp[sc * 20 + lane]) : make_float2(0.f, 0.f);
            s += pj;
            a0 += pj * zv.x;
            a1 += pj * zv.y;
        }
    }
    float inv = 1.f / s;
    float2 bb = act ? *(const float2*)&b2[lane * 2] : make_float2(0.f, 0.f);
    float v0 = act ? a0 * inv + bb.x : -1e30f;
    float v1 = act ? a1 * inv + bb.y : -1e30f;

    float mx = fmaxf(v0, v1);
#pragma unroll
    for (int o = 16; o > 0; o >>= 1) mx = fmaxf(mx, __shfl_xor_sync(0xffffffffu, mx, o));
    float sum = act ? (__expf(v0 - mx) + __expf(v1 - mx)) : 0.f;
#pragma unroll
    for (int o = 16; o > 0; o >>= 1) sum += __shfl_xor_sync(0xffffffffu, sum, o);
    float lse = __logf(sum);
    if (act)
        *(float2*)&out[d * OUTD + lane * 2] = make_float2(v0 - mx - lse, v1 - mx - lse);
}

// ---------------- launcher ----------------
extern "C" void kernel_launch(void* const* d_in, const int* in_sizes, int n_in,
                              void* d_out, int out_size) {
    const float* x   = (const float*)d_in[0];
    const int*   ei  = (const int*)d_in[1];
    const float* W1  = (const float*)d_in[2];
    const float* as1 = (const float*)d_in[3];
    const float* ad1 = (const float*)d_in[4];
    const float* b1  = (const float*)d_in[5];
    const float* W2  = (const float*)d_in[6];
    const float* as2 = (const float*)d_in[7];
    const float* ad2 = (const float*)d_in[8];
    const float* b2  = (const float*)d_in[9];
    float* out = (float*)d_out;
    (void)in_sizes; (void)n_in; (void)out_size;

    static bool attr_set = false;
    if (!attr_set) {
        cudaFuncSetAttribute(gemm2_kernel, cudaFuncAttributeMaxDynamicSharedMemorySize,
                             (40 * 132 + 128 * 132) * 4);
        attr_set = true;
    }

    zero_cnt_kernel<<<Z_BLOCKS, 256>>>();
    // K1: gemm1 || hist
    gemm1_hist_kernel<<<G1_BLOCKS + HIST_BLOCKS, 256>>>(x, W1, ei);
    // K2: scanA || al1
    al1_scanA_kernel<<<SCAN_BLOCKS + AL1_BLOCKS, 256>>>(as1, ad1);
    scanC_kernel<<<SCAN_BLOCKS, 256>>>();
    scatter_kernel<<<HIST_BLOCKS, 256>>>(ei);

    // layer 1 aggregation
    gat1_kernel<<<(Nn + 7) / 8, 256>>>(b1);

    // layer 2
    gemm2_kernel<<<(Nn + 127) / 128, 256, (40 * 132 + 128 * 132) * 4>>>(W2, as2, ad2);
    gat2_kernel<<<(Nn + 7) / 8, 256>>>(b2, out);
}

// round 11
// speedup vs baseline: 1.5045x; 1.0006x over previous
#include <cuda_runtime.h>
#include <cuda_bf16.h>

// ---------------- problem constants ----------------
#define Nn   50000
#define Ne   800000
#define IND  256
#define H1n  4
#define C1n  32
#define D1   128        // H1n*C1n
#define OUTD 40
#define NEG  0.2f

#define G1_BLOCKS 391           // ceil(50000/128)
#define Z_BLOCKS  49            // ceil(12500 int4 / 256)
#define AL1_BLOCKS 6250         // ceil(50000/8)
#define HIST_BLOCKS 782         // ceil(200000/256)
#define SCAN_BLOCKS 196         // ceil(50000/256)

// ---------------- scratch (device globals; no allocation allowed) -------
__device__ __align__(16) float g_h1[Nn * D1];            // x @ W1 (fp32)
__device__ __align__(16) __nv_bfloat162 g_h1b[Nn * 64];  // bf16 copy for gather
__device__ __align__(16) float g_h2[Nn * D1];            // elu(gat1 out)
__device__ __align__(16) __nv_bfloat16 g_z2b[Nn * OUTD]; // h2 @ W2 (bf16)
__device__ __align__(16) float g_als1[H1n * Nn];         // head-major
__device__ __align__(16) float g_ald1[H1n * Nn];         // head-major
__device__ float g_als2[Nn];
__device__ float g_ald2[Nn];
__device__ __align__(16) int g_cnt[Nn];
__device__ int   g_off[Nn + 1];
__device__ int   g_woff[Nn];
__device__ int   g_bsum[SCAN_BLOCKS];
__device__ int   g_csr[Ne];

// ---------------- helpers ----------------
__device__ __forceinline__ float lrelu(float x) { return x > 0.f ? x : NEG * x; }

__device__ __forceinline__ unsigned f2tf(float f) {
    unsigned r;
    asm("cvt.rna.tf32.f32 %0, %1;" : "=r"(r) : "f"(f));
    return r;
}

__device__ __forceinline__ void mma_tf32(float c[4],
                                         unsigned a0, unsigned a1, unsigned a2, unsigned a3,
                                         unsigned b0, unsigned b1) {
    asm volatile(
        "mma.sync.aligned.m16n8k8.row.col.f32.tf32.tf32.f32 "
        "{%0,%1,%2,%3},{%4,%5,%6,%7},{%8,%9},{%0,%1,%2,%3};"
        : "+f"(c[0]), "+f"(c[1]), "+f"(c[2]), "+f"(c[3])
        : "r"(a0), "r"(a1), "r"(a2), "r"(a3), "r"(b0), "r"(b1));
}

// ---------------- zero counts (tiny standalone so hist can overlap gemm1) ---
__global__ void zero_cnt_kernel() {
    int i = blockIdx.x * 256 + threadIdx.x;
    if (i * 4 < Nn) *(int4*)&g_cnt[i * 4] = make_int4(0, 0, 0, 0);
}

// =================================================================
// K1: gemm1 (blocks 0..390)  ||  hist (blocks 391..1172)
// =================================================================
#define G1_LOAD(K0)                                                                  \
    do {                                                                             \
        _Pragma("unroll") for (int i = 0; i < 4; i++) {                              \
            int idx = tid + i * 256;                                                 \
            int r = idx >> 3, c4 = idx & 7;                                          \
            int grow = rowBase + r;                                                  \
            pa[i] = (grow < Nn) ? *(const float4*)(x + grow * IND + (K0) + c4 * 4)   \
                                : make_float4(0.f, 0.f, 0.f, 0.f);                   \
        }                                                                            \
        _Pragma("unroll") for (int i = 0; i < 4; i++) {                              \
            int idx = tid + i * 256;                                                 \
            int r = idx >> 5, c4 = idx & 31;                                         \
            pb[i] = *(const float4*)(W + ((K0) + r) * D1 + c4 * 4);                  \
        }                                                                            \
    } while (0)

__global__ void gemm1_hist_kernel(const float* __restrict__ x, const float* __restrict__ W,
                                  const int* __restrict__ ei) {
    int tid = threadIdx.x;
    if (blockIdx.x >= G1_BLOCKS) {
        int base = ((blockIdx.x - G1_BLOCKS) * 256 + tid) * 4;
        if (base + 4 <= Ne) {
            int4 d = *(const int4*)&ei[Ne + base];
            atomicAdd(&g_cnt[d.x], 1);
            atomicAdd(&g_cnt[d.y], 1);
            atomicAdd(&g_cnt[d.z], 1);
            atomicAdd(&g_cnt[d.w], 1);
        } else {
            for (int e = base; e < Ne; e++) atomicAdd(&g_cnt[ei[Ne + e]], 1);
        }
        return;
    }
    __shared__ unsigned As[32][132];   // [k][m]
    __shared__ unsigned Bs[32][132];   // [k][n]
    int w = tid >> 5, lane = tid & 31;
    int gid = lane >> 2, tig = lane & 3;
    int mbase = (w & 3) * 32;
    int nbase = (w >> 2) * 64;
    int rowBase = blockIdx.x * 128;

    float acc[2][8][4];
#pragma unroll
    for (int mt = 0; mt < 2; mt++)
#pragma unroll
        for (int nt = 0; nt < 8; nt++)
#pragma unroll
            for (int i = 0; i < 4; i++) acc[mt][nt][i] = 0.f;

    float4 pa[4], pb[4];
    G1_LOAD(0);

    for (int k0 = 0; k0 < IND; k0 += 32) {
#pragma unroll
        for (int i = 0; i < 4; i++) {
            int idx = tid + i * 256;
            int r = idx >> 3, c4 = idx & 7;
            As[c4 * 4 + 0][r] = f2tf(pa[i].x);
            As[c4 * 4 + 1][r] = f2tf(pa[i].y);
            As[c4 * 4 + 2][r] = f2tf(pa[i].z);
            As[c4 * 4 + 3][r] = f2tf(pa[i].w);
        }
#pragma unroll
        for (int i = 0; i < 4; i++) {
            int idx = tid + i * 256;
            int r = idx >> 5, c4 = idx & 31;
            uint4 u;
            u.x = f2tf(pb[i].x); u.y = f2tf(pb[i].y); u.z = f2tf(pb[i].z); u.w = f2tf(pb[i].w);
            *(uint4*)&Bs[r][c4 * 4] = u;
        }
        __syncthreads();
        if (k0 + 32 < IND) G1_LOAD(k0 + 32);

#pragma unroll
        for (int kk = 0; kk < 4; kk++) {
            int k = kk * 8;
            unsigned a[2][4];
#pragma unroll
            for (int mt = 0; mt < 2; mt++) {
                int m0 = mbase + mt * 16 + gid;
                a[mt][0] = As[k + tig][m0];
                a[mt][1] = As[k + tig][m0 + 8];
                a[mt][2] = As[k + tig + 4][m0];
                a[mt][3] = As[k + tig + 4][m0 + 8];
            }
            unsigned b[8][2];
#pragma unroll
            for (int nt = 0; nt < 8; nt++) {
                int n0 = nbase + nt * 8 + gid;
                b[nt][0] = Bs[k + tig][n0];
                b[nt][1] = Bs[k + tig + 4][n0];
            }
#pragma unroll
            for (int mt = 0; mt < 2; mt++)
#pragma unroll
                for (int nt = 0; nt < 8; nt++)
                    mma_tf32(acc[mt][nt], a[mt][0], a[mt][1], a[mt][2], a[mt][3],
                             b[nt][0], b[nt][1]);
        }
        __syncthreads();
    }
#pragma unroll
    for (int mt = 0; mt < 2; mt++) {
        int r0 = rowBase + mbase + mt * 16 + gid;
#pragma unroll
        for (int nt = 0; nt < 8; nt++) {
            int col = nbase + nt * 8 + tig * 2;
            if (r0 < Nn) {
                *(float2*)&g_h1[r0 * D1 + col] = make_float2(acc[mt][nt][0], acc[mt][nt][1]);
                g_h1b[r0 * 64 + col / 2] = __floats2bfloat162_rn(acc[mt][nt][0], acc[mt][nt][1]);
            }
            if (r0 + 8 < Nn) {
                *(float2*)&g_h1[(r0 + 8) * D1 + col] = make_float2(acc[mt][nt][2], acc[mt][nt][3]);
                g_h1b[(r0 + 8) * 64 + col / 2] = __floats2bfloat162_rn(acc[mt][nt][2], acc[mt][nt][3]);
            }
        }
    }
}

// =================================================================
// K2: scanA (blocks 0..195, first so they start early)  ||  al1 (rest)
// =================================================================
__global__ void al1_scanA_kernel(const float* __restrict__ as1, const float* __restrict__ ad1) {
    int t = threadIdx.x;
    if (blockIdx.x < SCAN_BLOCKS) {
        int b = blockIdx.x;
        int i = b * 256 + t;
        int v = (i < Nn) ? g_cnt[i] : 0;
        int lane = t & 31, wid = t >> 5;
        int incl = v;
#pragma unroll
        for (int o = 1; o < 32; o <<= 1) {
            int n = __shfl_up_sync(0xffffffffu, incl, o);
            if (lane >= o) incl += n;
        }
        __shared__ int ws[8];
        if (lane == 31) ws[wid] = incl;
        __syncthreads();
        if (t < 8) {
            int w = ws[t];
#pragma unroll
            for (int o = 1; o < 8; o <<= 1) {
                int n = __shfl_up_sync(0xffu, w, o);
                if ((t & 7) >= o) w += n;
            }
            ws[t] = w;
        }
        __syncthreads();
        int excl = incl - v + (wid > 0 ? ws[wid - 1] : 0);
        if (i < Nn) g_off[i] = excl;
        if (t == 255) g_bsum[b] = excl + v;
        return;
    }
    int node = ((blockIdx.x - SCAN_BLOCKS) * 256 + t) >> 5;
    int lane = t & 31;
    if (node >= Nn) return;
    float4 h = *(const float4*)&g_h1[node * D1 + lane * 4];
    float4 a = *(const float4*)&as1[lane * 4];
    float4 b = *(const float4*)&ad1[lane * 4];
    float ps = h.x * a.x + h.y * a.y + h.z * a.z + h.w * a.w;
    float pd = h.x * b.x + h.y * b.y + h.z * b.z + h.w * b.w;
#pragma unroll
    for (int o = 4; o > 0; o >>= 1) {
        ps += __shfl_down_sync(0xffffffffu, ps, o, 8);
        pd += __shfl_down_sync(0xffffffffu, pd, o, 8);
    }
    if ((lane & 7) == 0) {
        int hd = lane >> 3;
        g_als1[hd * Nn + node] = ps;
        g_ald1[hd * Nn + node] = pd;
    }
}

__global__ void scanC_kernel() {
    int b = blockIdx.x, t = threadIdx.x;
    int v = (t < b) ? g_bsum[t] : 0;
    int lane = t & 31;
#pragma unroll
    for (int o = 16; o > 0; o >>= 1) v += __shfl_xor_sync(0xffffffffu, v, o);
    __shared__ int ws[8];
    if (lane == 0) ws[t >> 5] = v;
    __syncthreads();
    int off = 0;
#pragma unroll
    for (int k = 0; k < 8; k++) off += ws[k];
    int i = b * 256 + t;
    if (i < Nn) {
        int o = g_off[i] + off;
        g_off[i] = o;
        g_woff[i] = o;
    }
    if (b == 0 && t == 0) g_off[Nn] = Ne;
}

__global__ void scatter_kernel(const int* __restrict__ ei) {
    int base = (blockIdx.x * blockDim.x + threadIdx.x) * 4;
    if (base + 4 <= Ne) {
        int4 s = *(const int4*)&ei[base];
        int4 d = *(const int4*)&ei[Ne + base];
        int p0 = atomicAdd(&g_woff[d.x], 1);
        int p1 = atomicAdd(&g_woff[d.y], 1);
        int p2 = atomicAdd(&g_woff[d.z], 1);
        int p3 = atomicAdd(&g_woff[d.w], 1);
        g_csr[p0] = s.x;
        g_csr[p1] = s.y;
        g_csr[p2] = s.z;
        g_csr[p3] = s.w;
    } else {
        for (int e = base; e < Ne; e++) {
            int p = atomicAdd(&g_woff[ei[Ne + e]], 1);
            g_csr[p] = ei[e];
        }
    }
}

// ---------------- layer-1 GAT: warp per dst, bf16 gather ----------------
__global__ void gat1_kernel(const float* __restrict__ b1) {
    int d = (blockIdx.x * blockDim.x + threadIdx.x) >> 5;
    int lane = threadIdx.x & 31;
    if (d >= Nn) return;
    int hd = lane >> 3;
    int sub = lane & 7;
    int grp = lane & 24;

    const float* __restrict__ als_h = &g_als1[hd * Nn];
    float aldh = g_ald1[hd * Nn + d];
    float pe = __expf(lrelu(als_h[d] + aldh));
    float s = pe;
    float4 hv = *(const float4*)&g_h1[d * D1 + lane * 4];  // self: fp32 exact
    float a0 = pe * hv.x, a1 = pe * hv.y, a2 = pe * hv.z, a3 = pe * hv.w;

    int beg = g_off[d];
    int deg = g_off[d + 1] - beg;

    for (int base = 0; base < deg; base += 8) {
        int idx = base + sub;
        bool valid = idx < deg;
        int sc_l = valid ? g_csr[beg + idx] : 0;
        float pj_l = valid ? __expf(lrelu(als_h[sc_l] + aldh)) : 0.f;
#pragma unroll
        for (int j = 0; j < 8; j++) {
            int sc = __shfl_sync(0xffffffffu, sc_l, grp + j);
            float pj = __shfl_sync(0xffffffffu, pj_l, grp + j);
            const __nv_bfloat162* p = &g_h1b[sc * 64 + lane * 2];
            float2 x01 = __bfloat1622float2(p[0]);
            float2 x23 = __bfloat1622float2(p[1]);
            s += pj;
            a0 += pj * x01.x;
            a1 += pj * x01.y;
            a2 += pj * x23.x;
            a3 += pj * x23.y;
        }
    }
    float inv = 1.f / s;
    float4 bb = *(const float4*)&b1[lane * 4];
    float v0 = a0 * inv + bb.x;
    float v1 = a1 * inv + bb.y;
    float v2 = a2 * inv + bb.z;
    float v3 = a3 * inv + bb.w;
    v0 = v0 > 0.f ? v0 : __expf(v0) - 1.f;
    v1 = v1 > 0.f ? v1 : __expf(v1) - 1.f;
    v2 = v2 > 0.f ? v2 : __expf(v2) - 1.f;
    v3 = v3 > 0.f ? v3 : __expf(v3) - 1.f;
    *(float4*)&g_h2[d * D1 + lane * 4] = make_float4(v0, v1, v2, v3);
}

// ---------------- GEMM2 + fused layer-2 logits (bf16 z2 output) ----------------
__global__ void gemm2_kernel(const float* __restrict__ W2,
                             const float* __restrict__ as2,
                             const float* __restrict__ ad2) {
    extern __shared__ float sm2[];
    float* sWt = sm2;               // [40][132]
    float* sRow = sm2 + 40 * 132;   // [128][132]
    int tid = threadIdx.x;
    int nodeBase = blockIdx.x * 128;

    for (int i = tid; i < OUTD * D1; i += 256) {
        int c = i >> 7, k = i & 127;
        sWt[c * 132 + k] = W2[k * OUTD + c];
    }
#pragma unroll
    for (int i = 0; i < 16; i++) {
        int idx = tid + i * 256;
        int r = idx >> 5, c4 = idx & 31;
        int n = nodeBase + r;
        float4 v = make_float4(0.f, 0.f, 0.f, 0.f);
        if (n < Nn) v = *(const float4*)&g_h2[n * D1 + c4 * 4];
        *(float4*)&sRow[r * 132 + c4 * 4] = v;
    }
    __syncthreads();

    int r = tid >> 3, c0 = (tid & 7) * 5;
    float acc[4][5];
#pragma unroll
    for (int rr = 0; rr < 4; rr++)
#pragma unroll
        for (int c = 0; c < 5; c++) acc[rr][c] = 0.f;

    for (int k4 = 0; k4 < 32; k4++) {
        float4 wv[5];
#pragma unroll
        for (int c = 0; c < 5; c++) wv[c] = *(const float4*)&sWt[(c0 + c) * 132 + k4 * 4];
#pragma unroll
        for (int rr = 0; rr < 4; rr++) {
            float4 hv = *(const float4*)&sRow[(r + rr * 32) * 132 + k4 * 4];
#pragma unroll
            for (int c = 0; c < 5; c++)
                acc[rr][c] += hv.x * wv[c].x + hv.y * wv[c].y + hv.z * wv[c].z + hv.w * wv[c].w;
        }
    }
    float a_s[5], a_d[5];
#pragma unroll
    for (int c = 0; c < 5; c++) { a_s[c] = as2[c0 + c]; a_d[c] = ad2[c0 + c]; }
#pragma unroll
    for (int rr = 0; rr < 4; rr++) {
        int n = nodeBase + r + rr * 32;
        if (n < Nn) {
#pragma unroll
            for (int c = 0; c < 5; c++)
                g_z2b[n * OUTD + c0 + c] = __float2bfloat16_rn(acc[rr][c]);
        }
        float ps = 0.f, pd = 0.f;
#pragma unroll
        for (int c = 0; c < 5; c++) { ps += acc[rr][c] * a_s[c]; pd += acc[rr][c] * a_d[c]; }
#pragma unroll
        for (int o = 4; o > 0; o >>= 1) {
            ps += __shfl_down_sync(0xffffffffu, ps, o, 8);
            pd += __shfl_down_sync(0xffffffffu, pd, o, 8);
        }
        if ((tid & 7) == 0 && n < Nn) {
            g_als2[n] = ps;
            g_ald2[n] = pd;
        }
    }
}

// ---------------- layer-2 GAT (bf16 gather, lane<20 holds classes 2l,2l+1) ----
__global__ void gat2_kernel(const float* __restrict__ b2, float* __restrict__ out) {
    int d = (blockIdx.x * blockDim.x + threadIdx.x) >> 5;
    int lane = threadIdx.x & 31;
    if (d >= Nn) return;
    int sub = lane & 7;
    bool act = lane < 20;
    const __nv_bfloat162* __restrict__ zp = (const __nv_bfloat162*)g_z2b;

    float ald = g_ald2[d];
    float pe = __expf(lrelu(g_als2[d] + ald));
    float s = pe;
    float2 zs = act ? __bfloat1622float2(zp[d * 20 + lane]) : make_float2(0.f, 0.f);
    float a0 = pe * zs.x, a1 = pe * zs.y;

    int beg = g_off[d];
    int deg = g_off[d + 1] - beg;

    for (int base = 0; base < deg; base += 8) {
        int idx = base + sub;
        bool valid = idx < deg;
        int sc_l = valid ? g_csr[beg + idx] : 0;
        float pj_l = valid ? __expf(lrelu(g_als2[sc_l] + ald)) : 0.f;
#pragma unroll
        for (int j = 0; j < 8; j++) {
            int sc = __shfl_sync(0xffffffffu, sc_l, j);
            float pj = __shfl_sync(0xffffffffu, pj_l, j);
            float2 zv = act ? __bfloat1622float2(zp[sc * 20 + lane]) : make_float2(0.f, 0.f);
            s += pj;
            a0 += pj * zv.x;
            a1 += pj * zv.y;
        }
    }
    float inv = 1.f / s;
    float2 bb = act ? *(const float2*)&b2[lane * 2] : make_float2(0.f, 0.f);
    float v0 = act ? a0 * inv + bb.x : -1e30f;
    float v1 = act ? a1 * inv + bb.y : -1e30f;

    float mx = fmaxf(v0, v1);
#pragma unroll
    for (int o = 16; o > 0; o >>= 1) mx = fmaxf(mx, __shfl_xor_sync(0xffffffffu, mx, o));
    float sum = act ? (__expf(v0 - mx) + __expf(v1 - mx)) : 0.f;
#pragma unroll
    for (int o = 16; o > 0; o >>= 1) sum += __shfl_xor_sync(0xffffffffu, sum, o);
    float lse = __logf(sum);
    if (act)
        *(float2*)&out[d * OUTD + lane * 2] = make_float2(v0 - mx - lse, v1 - mx - lse);
}

// ---------------- launcher ----------------
extern "C" void kernel_launch(void* const* d_in, const int* in_sizes, int n_in,
                              void* d_out, int out_size) {
    const float* x   = (const float*)d_in[0];
    const int*   ei  = (const int*)d_in[1];
    const float* W1  = (const float*)d_in[2];
    const float* as1 = (const float*)d_in[3];
    const float* ad1 = (const float*)d_in[4];
    const float* b1  = (const float*)d_in[5];
    const float* W2  = (const float*)d_in[6];
    const float* as2 = (const float*)d_in[7];
    const float* ad2 = (const float*)d_in[8];
    const float* b2  = (const float*)d_in[9];
    float* out = (float*)d_out;
    (void)in_sizes; (void)n_in; (void)out_size;

    static bool attr_set = false;
    if (!attr_set) {
        cudaFuncSetAttribute(gemm2_kernel, cudaFuncAttributeMaxDynamicSharedMemorySize,
                             (40 * 132 + 128 * 132) * 4);
        attr_set = true;
    }

    zero_cnt_kernel<<<Z_BLOCKS, 256>>>();
    // K1: gemm1 || hist
    gemm1_hist_kernel<<<G1_BLOCKS + HIST_BLOCKS, 256>>>(x, W1, ei);
    // K2: scanA || al1
    al1_scanA_kernel<<<SCAN_BLOCKS + AL1_BLOCKS, 256>>>(as1, ad1);
    scanC_kernel<<<SCAN_BLOCKS, 256>>>();
    scatter_kernel<<<HIST_BLOCKS, 256>>>(ei);

    // layer 1 aggregation
    gat1_kernel<<<(Nn + 7) / 8, 256>>>(b1);

    // layer 2
    gemm2_kernel<<<(Nn + 127) / 128, 256, (40 * 132 + 128 * 132) * 4>>>(W2, as2, ad2);
    gat2_kernel<<<(Nn + 7) / 8, 256>>>(b2, out);
}